// round 5
// baseline (speedup 1.0000x reference)
#include <cuda_runtime.h>
#include <cuda_bf16.h>
#include <math.h>
#include <cstdint>

#define BSZ 512
#define FD  512
#define HD  512
#define ED  8
#define OD  512

// ---------------- scratch (device globals; allocation is forbidden) ----------------
__device__ float d_h2[BSZ * HD];
__device__ float d_g [BSZ * ED];
__device__ float d_T [ED * BSZ * HD];

__device__ __align__(16) __nv_bfloat16 d_xhi[BSZ * FD], d_xlo[BSZ * FD];
__device__ __align__(16) __nv_bfloat16 d_ahi[BSZ * FD], d_alo[BSZ * FD];
__device__ __align__(16) __nv_bfloat16 d_g0hi[HD * FD], d_g0lo[HD * FD];
__device__ __align__(16) __nv_bfloat16 d_g1hi[HD * HD], d_g1lo[HD * HD];
__device__ __align__(16) __nv_bfloat16 d_w0hi[ED * HD * FD], d_w0lo[ED * HD * FD];
__device__ __align__(16) __nv_bfloat16 d_w1hi[ED * HD * HD], d_w1lo[ED * HD * HD];
__device__ __align__(16) __nv_bfloat16 d_w2hi[ED * OD * HD], d_w2lo[ED * OD * HD];

__device__ __forceinline__ float elu1(float v) { return v > 0.f ? v : expm1f(v); }

__device__ __forceinline__ uint32_t smem_u32(const void* p) {
    uint32_t a;
    asm("{ .reg .u64 t; cvta.to.shared.u64 t, %1; cvt.u32.u64 %0, t; }" : "=r"(a) : "l"(p));
    return a;
}

#define CP16(dst, src) \
    asm volatile("cp.async.cg.shared.global [%0], [%1], 16;" :: "r"(dst), "l"(src))

#define LDSM4(r, addr) \
    asm volatile("ldmatrix.sync.aligned.m8n8.x4.shared.b16 {%0,%1,%2,%3}, [%4];" \
                 : "=r"((r)[0]), "=r"((r)[1]), "=r"((r)[2]), "=r"((r)[3]) : "r"(addr))

#define MMA16816(d, a, b0, b1) \
    asm volatile("mma.sync.aligned.m16n8k16.row.col.f32.bf16.bf16.f32 " \
                 "{%0,%1,%2,%3},{%4,%5,%6,%7},{%8,%9},{%0,%1,%2,%3};" \
                 : "+f"((d)[0]), "+f"((d)[1]), "+f"((d)[2]), "+f"((d)[3]) \
                 : "r"((a)[0]), "r"((a)[1]), "r"((a)[2]), "r"((a)[3]), "r"(b0), "r"(b1))

__device__ __forceinline__ uint32_t pack_bf16x2(float a, float b) {
    uint32_t r;
    asm("cvt.rn.bf16x2.f32 %0, %1, %2;" : "=r"(r) : "f"(b), "f"(a));
    return r;
}

// ---------------- split-conversion: fp32 -> (hi, lo) bf16, 4 float4/thread ----------------
__global__ void __launch_bounds__(256)
conv_split(const float4* __restrict__ in, uint2* __restrict__ hi, uint2* __restrict__ lo, int n4) {
    const int base = blockIdx.x * 1024 + threadIdx.x;
    float4 v[4];
    #pragma unroll
    for (int k = 0; k < 4; k++) {
        const int i = base + k * 256;
        if (i < n4) v[k] = in[i];
    }
    #pragma unroll
    for (int k = 0; k < 4; k++) {
        const int i = base + k * 256;
        if (i >= n4) continue;
        float h0 = __bfloat162float(__float2bfloat16(v[k].x));
        float h1 = __bfloat162float(__float2bfloat16(v[k].y));
        float h2 = __bfloat162float(__float2bfloat16(v[k].z));
        float h3 = __bfloat162float(__float2bfloat16(v[k].w));
        uint2 H, L;
        H.x = pack_bf16x2(h0, h1); H.y = pack_bf16x2(h2, h3);
        L.x = pack_bf16x2(v[k].x - h0, v[k].y - h1);
        L.y = pack_bf16x2(v[k].z - h2, v[k].w - h3);
        hi[i] = H; lo[i] = L;
    }
}

// ---------------- fused 3-pass split GEMM, 128x128 tile (expert layers) ----------------
// acc = Ahi·Bhi^T + Alo·Bhi^T + Ahi·Blo^T over K=512, BK=64, 3-stage cp.async.
// mode: 0 = plain fp32 out; 1 = bias+elu fp32 out; 2 = bias+elu, split bf16 hi/lo out.
__global__ void __launch_bounds__(256)
tgemm_fused(const __nv_bfloat16* __restrict__ Axhi, const __nv_bfloat16* __restrict__ Axlo,
            const __nv_bfloat16* __restrict__ Bwhi, const __nv_bfloat16* __restrict__ Bwlo,
            const float* __restrict__ bias, float* __restrict__ C,
            __nv_bfloat16* __restrict__ Ohi, __nv_bfloat16* __restrict__ Olo,
            long strideW, long strideC, int mode)
{
    extern __shared__ __align__(128) char smem[];
    const uint32_t sb = smem_u32(smem);
    const int tid = threadIdx.x;
    const int wid = tid >> 5, lane = tid & 31;
    const int e = blockIdx.z;
    const int bm = blockIdx.y * 128, bn = blockIdx.x * 128;
    Bwhi += (long)e * strideW;
    Bwlo += (long)e * strideW;
    C    += (long)e * strideC;

    const int lsub = tid >> 3;   // 0..31
    const int lc16 = tid & 7;

    const __nv_bfloat16* tp[4] = { Axhi, Axlo, Bwhi, Bwlo };
    const int toff[4] = { bm, bm, bn, bn };

    auto load_stage = [&](int kc, int buf) {
        const int k0 = kc << 6;
        const uint32_t base = sb + (uint32_t)buf * 65536u;
        #pragma unroll
        for (int t = 0; t < 4; t++) {
            const __nv_bfloat16* P = tp[t];
            #pragma unroll
            for (int it = 0; it < 4; it++) {
                const int row = it * 32 + lsub;
                const uint32_t dst = base + (uint32_t)t * 16384u
                                   + (uint32_t)(row * 128 + ((lc16 ^ (row & 7)) << 4));
                CP16(dst, P + (long)(toff[t] + row) * 512 + k0 + lc16 * 8);
            }
        }
    };

    const int warpM = wid & 3, warpN = wid >> 2;
    const int arow = warpM * 32 + (lane & 15);
    const uint32_t aswz = (uint32_t)(arow & 7);
    const uint32_t ahalf = (uint32_t)(lane >> 4);
    const int q = lane >> 3;
    const int brow_base = warpN * 64 + ((q >> 1) << 3) + (lane & 7);
    const uint32_t bk = (uint32_t)(q & 1);

    float acc[2][8][4] = {};

    load_stage(0, 0);
    asm volatile("cp.async.commit_group;" ::: "memory");
    load_stage(1, 1);
    asm volatile("cp.async.commit_group;" ::: "memory");

    for (int c = 0; c < 8; c++) {
        if (c < 7) asm volatile("cp.async.wait_group 1;" ::: "memory");
        else       asm volatile("cp.async.wait_group 0;" ::: "memory");
        __syncthreads();
        if (c + 2 < 8) {
            load_stage(c + 2, (c + 2) % 3);
            asm volatile("cp.async.commit_group;" ::: "memory");
        }

        const uint32_t S   = sb + (uint32_t)(c % 3) * 65536u;
        const uint32_t Ahi = S, Alo = S + 16384u, Bhi = S + 32768u, Blo = S + 49152u;

        #pragma unroll
        for (int ks = 0; ks < 4; ks++) {
            const uint32_t achunk = (((uint32_t)(ks << 1) + ahalf) ^ aswz) << 4;
            uint32_t ah[2][4], al[2][4];
            #pragma unroll
            for (int mi = 0; mi < 2; mi++) {
                const uint32_t roff = (uint32_t)((arow + mi * 16) * 128);
                LDSM4(ah[mi], Ahi + roff + achunk);
                LDSM4(al[mi], Alo + roff + achunk);
            }
            uint32_t b[4][4];
            #pragma unroll
            for (int np = 0; np < 4; np++) {
                const int brow = brow_base + np * 16;
                const uint32_t boff = (uint32_t)(brow * 128)
                                    + ((((uint32_t)(ks << 1) + bk) ^ (uint32_t)(brow & 7)) << 4);
                LDSM4(b[np], Bhi + boff);
            }
            #pragma unroll
            for (int mi = 0; mi < 2; mi++)
                #pragma unroll
                for (int ni = 0; ni < 8; ni++) {
                    MMA16816(acc[mi][ni], ah[mi], b[ni >> 1][(ni & 1) * 2],
                             b[ni >> 1][(ni & 1) * 2 + 1]);
                    MMA16816(acc[mi][ni], al[mi], b[ni >> 1][(ni & 1) * 2],
                             b[ni >> 1][(ni & 1) * 2 + 1]);
                }
            #pragma unroll
            for (int np = 0; np < 4; np++) {
                const int brow = brow_base + np * 16;
                const uint32_t boff = (uint32_t)(brow * 128)
                                    + ((((uint32_t)(ks << 1) + bk) ^ (uint32_t)(brow & 7)) << 4);
                LDSM4(b[np], Blo + boff);
            }
            #pragma unroll
            for (int mi = 0; mi < 2; mi++)
                #pragma unroll
                for (int ni = 0; ni < 8; ni++)
                    MMA16816(acc[mi][ni], ah[mi], b[ni >> 1][(ni & 1) * 2],
                             b[ni >> 1][(ni & 1) * 2 + 1]);
        }
        __syncthreads();
    }

    const int gr = lane >> 2, gc = (lane & 3) * 2;
    #pragma unroll
    for (int mi = 0; mi < 2; mi++) {
        const int row0 = bm + warpM * 32 + mi * 16 + gr;
        #pragma unroll
        for (int ni = 0; ni < 8; ni++) {
            const int col = bn + warpN * 64 + ni * 8 + gc;
            float v0 = acc[mi][ni][0], v1 = acc[mi][ni][1];
            float v2 = acc[mi][ni][2], v3 = acc[mi][ni][3];
            if (mode != 0) {
                const float b0 = bias[col], b1 = bias[col + 1];
                v0 = elu1(v0 + b0); v1 = elu1(v1 + b1);
                v2 = elu1(v2 + b0); v3 = elu1(v3 + b1);
            }
            if (mode == 2) {
                float h0f = __bfloat162float(__float2bfloat16(v0));
                float h1f = __bfloat162float(__float2bfloat16(v1));
                float h2f = __bfloat162float(__float2bfloat16(v2));
                float h3f = __bfloat162float(__float2bfloat16(v3));
                *(uint32_t*)&Ohi[(long)row0 * 512 + col]       = pack_bf16x2(h0f, h1f);
                *(uint32_t*)&Olo[(long)row0 * 512 + col]       = pack_bf16x2(v0 - h0f, v1 - h1f);
                *(uint32_t*)&Ohi[(long)(row0 + 8) * 512 + col] = pack_bf16x2(h2f, h3f);
                *(uint32_t*)&Olo[(long)(row0 + 8) * 512 + col] = pack_bf16x2(v2 - h2f, v3 - h3f);
            } else {
                *(float2*)&C[(long)row0 * 512 + col]       = make_float2(v0, v1);
                *(float2*)&C[(long)(row0 + 8) * 512 + col] = make_float2(v2, v3);
            }
        }
    }
}

// ---------------- fused 3-pass split GEMM, 64x64 tile (gating layers) ----------------
// 128 threads, 4 warps (2x2), warp tile 32x32; grid (8,8) = 64 CTAs.
__global__ void __launch_bounds__(128)
tgemm64(const __nv_bfloat16* __restrict__ Axhi, const __nv_bfloat16* __restrict__ Axlo,
        const __nv_bfloat16* __restrict__ Bwhi, const __nv_bfloat16* __restrict__ Bwlo,
        const float* __restrict__ bias, float* __restrict__ C,
        __nv_bfloat16* __restrict__ Ohi, __nv_bfloat16* __restrict__ Olo, int mode)
{
    extern __shared__ __align__(128) char smem[];
    const uint32_t sb = smem_u32(smem);
    const int tid = threadIdx.x;
    const int wid = tid >> 5, lane = tid & 31;
    const int bm = blockIdx.y * 64, bn = blockIdx.x * 64;

    const int lsub = tid >> 3;   // 0..15
    const int lc16 = tid & 7;

    const __nv_bfloat16* tp[4] = { Axhi, Axlo, Bwhi, Bwlo };
    const int toff[4] = { bm, bm, bn, bn };

    // stage: [Ahi 8K][Alo 8K][Bhi 8K][Blo 8K] = 32KB; 3 stages = 96KB
    auto load_stage = [&](int kc, int buf) {
        const int k0 = kc << 6;
        const uint32_t base = sb + (uint32_t)buf * 32768u;
        #pragma unroll
        for (int t = 0; t < 4; t++) {
            const __nv_bfloat16* P = tp[t];
            #pragma unroll
            for (int it = 0; it < 4; it++) {
                const int row = it * 16 + lsub;
                const uint32_t dst = base + (uint32_t)t * 8192u
                                   + (uint32_t)(row * 128 + ((lc16 ^ (row & 7)) << 4));
                CP16(dst, P + (long)(toff[t] + row) * 512 + k0 + lc16 * 8);
            }
        }
    };

    const int warpM = wid & 1, warpN = wid >> 1;
    const int arow = warpM * 32 + (lane & 15);
    const uint32_t aswz = (uint32_t)(arow & 7);
    const uint32_t ahalf = (uint32_t)(lane >> 4);
    const int q = lane >> 3;
    const int brow_base = warpN * 32 + ((q >> 1) << 3) + (lane & 7);
    const uint32_t bk = (uint32_t)(q & 1);

    float acc[2][4][4] = {};

    load_stage(0, 0);
    asm volatile("cp.async.commit_group;" ::: "memory");
    load_stage(1, 1);
    asm volatile("cp.async.commit_group;" ::: "memory");

    for (int c = 0; c < 8; c++) {
        if (c < 7) asm volatile("cp.async.wait_group 1;" ::: "memory");
        else       asm volatile("cp.async.wait_group 0;" ::: "memory");
        __syncthreads();
        if (c + 2 < 8) {
            load_stage(c + 2, (c + 2) % 3);
            asm volatile("cp.async.commit_group;" ::: "memory");
        }

        const uint32_t S   = sb + (uint32_t)(c % 3) * 32768u;
        const uint32_t Ahi = S, Alo = S + 8192u, Bhi = S + 16384u, Blo = S + 24576u;

        #pragma unroll
        for (int ks = 0; ks < 4; ks++) {
            const uint32_t achunk = (((uint32_t)(ks << 1) + ahalf) ^ aswz) << 4;
            uint32_t ah[2][4], al[2][4];
            #pragma unroll
            for (int mi = 0; mi < 2; mi++) {
                const uint32_t roff = (uint32_t)((arow + mi * 16) * 128);
                LDSM4(ah[mi], Ahi + roff + achunk);
                LDSM4(al[mi], Alo + roff + achunk);
            }
            uint32_t b[2][4];
            #pragma unroll
            for (int np = 0; np < 2; np++) {
                const int brow = brow_base + np * 16;
                const uint32_t boff = (uint32_t)(brow * 128)
                                    + ((((uint32_t)(ks << 1) + bk) ^ (uint32_t)(brow & 7)) << 4);
                LDSM4(b[np], Bhi + boff);
            }
            #pragma unroll
            for (int mi = 0; mi < 2; mi++)
                #pragma unroll
                for (int ni = 0; ni < 4; ni++) {
                    MMA16816(acc[mi][ni], ah[mi], b[ni >> 1][(ni & 1) * 2],
                             b[ni >> 1][(ni & 1) * 2 + 1]);
                    MMA16816(acc[mi][ni], al[mi], b[ni >> 1][(ni & 1) * 2],
                             b[ni >> 1][(ni & 1) * 2 + 1]);
                }
            #pragma unroll
            for (int np = 0; np < 2; np++) {
                const int brow = brow_base + np * 16;
                const uint32_t boff = (uint32_t)(brow * 128)
                                    + ((((uint32_t)(ks << 1) + bk) ^ (uint32_t)(brow & 7)) << 4);
                LDSM4(b[np], Blo + boff);
            }
            #pragma unroll
            for (int mi = 0; mi < 2; mi++)
                #pragma unroll
                for (int ni = 0; ni < 4; ni++)
                    MMA16816(acc[mi][ni], ah[mi], b[ni >> 1][(ni & 1) * 2],
                             b[ni >> 1][(ni & 1) * 2 + 1]);
        }
        __syncthreads();
    }

    const int gr = lane >> 2, gc = (lane & 3) * 2;
    #pragma unroll
    for (int mi = 0; mi < 2; mi++) {
        const int row0 = bm + warpM * 32 + mi * 16 + gr;
        #pragma unroll
        for (int ni = 0; ni < 4; ni++) {
            const int col = bn + warpN * 32 + ni * 8 + gc;
            float v0 = acc[mi][ni][0], v1 = acc[mi][ni][1];
            float v2 = acc[mi][ni][2], v3 = acc[mi][ni][3];
            const float b0 = bias[col], b1 = bias[col + 1];
            v0 = elu1(v0 + b0); v1 = elu1(v1 + b1);
            v2 = elu1(v2 + b0); v3 = elu1(v3 + b1);
            if (mode == 2) {
                float h0f = __bfloat162float(__float2bfloat16(v0));
                float h1f = __bfloat162float(__float2bfloat16(v1));
                float h2f = __bfloat162float(__float2bfloat16(v2));
                float h3f = __bfloat162float(__float2bfloat16(v3));
                *(uint32_t*)&Ohi[(long)row0 * 512 + col]       = pack_bf16x2(h0f, h1f);
                *(uint32_t*)&Olo[(long)row0 * 512 + col]       = pack_bf16x2(v0 - h0f, v1 - h1f);
                *(uint32_t*)&Ohi[(long)(row0 + 8) * 512 + col] = pack_bf16x2(h2f, h3f);
                *(uint32_t*)&Olo[(long)(row0 + 8) * 512 + col] = pack_bf16x2(v2 - h2f, v3 - h3f);
            } else {
                *(float2*)&C[(long)row0 * 512 + col]       = make_float2(v0, v1);
                *(float2*)&C[(long)(row0 + 8) * 512 + col] = make_float2(v2, v3);
            }
        }
    }
}

// ---------------- gating softmax ----------------
__global__ void __launch_bounds__(256)
gate_kernel(const float* __restrict__ h, const float* __restrict__ w2,
            const float* __restrict__ b2, float* __restrict__ g)
{
    __shared__ float s[512];
    __shared__ float lg[8];
    const int b = blockIdx.x, tid = threadIdx.x;
    for (int i = tid; i < 512; i += 256) s[i] = h[(long)b * 512 + i];
    __syncthreads();

    const int w = tid >> 5, lane = tid & 31;
    float sum = 0.f;
    for (int i = lane; i < 512; i += 32) sum += s[i] * w2[(long)w * 512 + i];
    #pragma unroll
    for (int o = 16; o > 0; o >>= 1) sum += __shfl_xor_sync(0xffffffffu, sum, o);
    if (lane == 0) lg[w] = sum + b2[w];
    __syncthreads();

    if (tid == 0) {
        float mx = lg[0];
        #pragma unroll
        for (int i = 1; i < 8; i++) mx = fmaxf(mx, lg[i]);
        float ex[8], se = 0.f;
        #pragma unroll
        for (int i = 0; i < 8; i++) { ex[i] = expf(lg[i] - mx); se += ex[i]; }
        float inv = 1.f / se;
        #pragma unroll
        for (int i = 0; i < 8; i++) g[(long)b * 8 + i] = ex[i] * inv;
    }
}

// ---------------- gated blend (2x float4/thread) ----------------
__global__ void __launch_bounds__(256)
blend_kernel(const float4* __restrict__ T4, const float* __restrict__ g,
             const float4* __restrict__ beta4, float* __restrict__ out,
             __nv_bfloat16* __restrict__ Ohi, __nv_bfloat16* __restrict__ Olo, int mode)
{
    #pragma unroll
    for (int kk = 0; kk < 2; kk++) {
        const int i4 = blockIdx.x * 512 + kk * 256 + threadIdx.x;
        const int base = i4 << 2;
        const int b = base >> 9, h4 = (base & 511) >> 2;
        float4 sum = make_float4(0.f, 0.f, 0.f, 0.f);
        #pragma unroll
        for (int e = 0; e < 8; e++) {
            const float ge = g[b * 8 + e];
            const float4 t = T4[(e << 16) + i4];
            const float4 be = beta4[(e << 7) + h4];
            sum.x += ge * (t.x + be.x); sum.y += ge * (t.y + be.y);
            sum.z += ge * (t.z + be.z); sum.w += ge * (t.w + be.w);
        }
        if (mode == 0) {
            ((float4*)out)[i4] = sum;
        } else {
            sum.x = elu1(sum.x); sum.y = elu1(sum.y); sum.z = elu1(sum.z); sum.w = elu1(sum.w);
            float h0 = __bfloat162float(__float2bfloat16(sum.x));
            float h1 = __bfloat162float(__float2bfloat16(sum.y));
            float h2 = __bfloat162float(__float2bfloat16(sum.z));
            float h3 = __bfloat162float(__float2bfloat16(sum.w));
            uint2 H, L;
            H.x = pack_bf16x2(h0, h1); H.y = pack_bf16x2(h2, h3);
            L.x = pack_bf16x2(sum.x - h0, sum.y - h1);
            L.y = pack_bf16x2(sum.z - h2, sum.w - h3);
            ((uint2*)Ohi)[i4] = H;
            ((uint2*)Olo)[i4] = L;
        }
    }
}

// ---------------- launch ----------------
extern "C" void kernel_launch(void* const* d_in, const int* in_sizes, int n_in,
                              void* d_out, int out_size)
{
    const float* x      = (const float*)d_in[0];
    const float* gw0    = (const float*)d_in[1];
    const float* gb0    = (const float*)d_in[2];
    const float* gw1    = (const float*)d_in[3];
    const float* gb1    = (const float*)d_in[4];
    const float* gw2    = (const float*)d_in[5];
    const float* gb2    = (const float*)d_in[6];
    const float* alpha0 = (const float*)d_in[7];
    const float* beta0  = (const float*)d_in[8];
    const float* alpha1 = (const float*)d_in[9];
    const float* beta1  = (const float*)d_in[10];
    const float* alpha2 = (const float*)d_in[11];
    const float* beta2  = (const float*)d_in[12];
    float* out = (float*)d_out;

    float *h2, *gp, *T;
    cudaGetSymbolAddress((void**)&h2, d_h2);
    cudaGetSymbolAddress((void**)&gp, d_g);
    cudaGetSymbolAddress((void**)&T,  d_T);

    __nv_bfloat16 *xhi, *xlo, *ahi, *alo, *g0hi, *g0lo, *g1hi, *g1lo;
    __nv_bfloat16 *w0hi, *w0lo, *w1hi, *w1lo, *w2hi, *w2lo;
    cudaGetSymbolAddress((void**)&xhi,  d_xhi);  cudaGetSymbolAddress((void**)&xlo,  d_xlo);
    cudaGetSymbolAddress((void**)&ahi,  d_ahi);  cudaGetSymbolAddress((void**)&alo,  d_alo);
    cudaGetSymbolAddress((void**)&g0hi, d_g0hi); cudaGetSymbolAddress((void**)&g0lo, d_g0lo);
    cudaGetSymbolAddress((void**)&g1hi, d_g1hi); cudaGetSymbolAddress((void**)&g1lo, d_g1lo);
    cudaGetSymbolAddress((void**)&w0hi, d_w0hi); cudaGetSymbolAddress((void**)&w0lo, d_w0lo);
    cudaGetSymbolAddress((void**)&w1hi, d_w1hi); cudaGetSymbolAddress((void**)&w1lo, d_w1lo);
    cudaGetSymbolAddress((void**)&w2hi, d_w2hi); cudaGetSymbolAddress((void**)&w2lo, d_w2lo);

    const int SMEM_SZ   = 3 * 65536;  // 128-tile: 3 stages x 64KB
    const int SMEM_SZ64 = 3 * 32768;  // 64-tile: 3 stages x 32KB
    cudaFuncSetAttribute(tgemm_fused, cudaFuncAttributeMaxDynamicSharedMemorySize, SMEM_SZ);
    cudaFuncSetAttribute(tgemm64, cudaFuncAttributeMaxDynamicSharedMemorySize, SMEM_SZ64);

    const int NSMALL4 = (512 * 512) / 4;
    const int NBIG4   = (8 * 512 * 512) / 4;
    const long sW = 512L * 512, sC = 512L * 512;
    dim3 gG(8, 8, 1), g8(4, 4, 8);
    const int BLEND_B = (BSZ * HD / 4) / 512;  // 128 blocks

    // split conversions (inputs + weights); 1024 float4 per block
    conv_split<<<NSMALL4 / 1024, 256>>>((const float4*)x,   (uint2*)xhi,  (uint2*)xlo,  NSMALL4);
    conv_split<<<NSMALL4 / 1024, 256>>>((const float4*)gw0, (uint2*)g0hi, (uint2*)g0lo, NSMALL4);
    conv_split<<<NSMALL4 / 1024, 256>>>((const float4*)gw1, (uint2*)g1hi, (uint2*)g1lo, NSMALL4);
    conv_split<<<NBIG4 / 1024, 256>>>((const float4*)alpha0, (uint2*)w0hi, (uint2*)w0lo, NBIG4);
    conv_split<<<NBIG4 / 1024, 256>>>((const float4*)alpha1, (uint2*)w1hi, (uint2*)w1lo, NBIG4);
    conv_split<<<NBIG4 / 1024, 256>>>((const float4*)alpha2, (uint2*)w2hi, (uint2*)w2lo, NBIG4);

    // gating MLP (64x64-tile kernels; layer1 writes split bf16, layer2 fp32)
    tgemm64<<<gG, 128, SMEM_SZ64>>>(xhi, xlo, g0hi, g0lo, gb0, nullptr, ahi, alo, 2);
    tgemm64<<<gG, 128, SMEM_SZ64>>>(ahi, alo, g1hi, g1lo, gb1, h2, nullptr, nullptr, 1);
    gate_kernel<<<BSZ, 256>>>(h2, gw2, gb2, gp);

    // expert layer 1
    tgemm_fused<<<g8, 256, SMEM_SZ>>>(xhi, xlo, w0hi, w0lo, nullptr, T, nullptr, nullptr, sW, sC, 0);
    blend_kernel<<<BLEND_B, 256>>>((const float4*)T, gp, (const float4*)beta0, nullptr, ahi, alo, 1);

    // expert layer 2
    tgemm_fused<<<g8, 256, SMEM_SZ>>>(ahi, alo, w1hi, w1lo, nullptr, T, nullptr, nullptr, sW, sC, 0);
    blend_kernel<<<BLEND_B, 256>>>((const float4*)T, gp, (const float4*)beta1, nullptr, ahi, alo, 1);

    // expert layer 3 (final: fp32, no activation)
    tgemm_fused<<<g8, 256, SMEM_SZ>>>(ahi, alo, w2hi, w2lo, nullptr, T, nullptr, nullptr, sW, sC, 0);
    blend_kernel<<<BLEND_B, 256>>>((const float4*)T, gp, (const float4*)beta2, out, nullptr, nullptr, 0);
}